// round 12
// baseline (speedup 1.0000x reference)
#include <cuda_runtime.h>
#include <math.h>

// ---------------- problem constants ----------------
#define MB      512
#define NN      100
#define TT      100
#define LL      50
#define HE      64
#define EE      128
#define NE      512
#define HD      256
#define MTOT    (MB*NN)     // 51200
#define BETA    0.25f

#define XH_ELEMS   (MTOT*TT)        // 5,120,000
#define OFF_RECON  (XH_ELEMS)
#define OFF_VQ     (XH_ELEMS+1)
#define OFF_IDX    (XH_ELEMS+2)

typedef unsigned long long u64;

// ---- f32x2 helpers ----
__device__ __forceinline__ u64 pk2(float lo, float hi) {
    u64 r;
    asm("mov.b64 %0, {%1, %2};" : "=l"(r) : "r"(__float_as_uint(lo)), "r"(__float_as_uint(hi)));
    return r;
}
__device__ __forceinline__ void upk2(u64 v, float& lo, float& hi) {
    unsigned a, b;
    asm("mov.b64 {%0, %1}, %2;" : "=r"(a), "=r"(b) : "l"(v));
    lo = __uint_as_float(a); hi = __uint_as_float(b);
}
__device__ __forceinline__ u64 fma2(u64 a, u64 b, u64 c) {
    u64 d;
    asm("fma.rn.f32x2 %0, %1, %2, %3;" : "=l"(d) : "l"(a), "l"(b), "l"(c));
    return d;
}

// ---------------- device scratch ----------------
__device__ float g_z[MTOT*EE];
__device__ int   g_idx[MTOT];
__device__ float g_cnorm[NE];
__device__ float g_acc[4];
__device__ int   g_afirst_is_x;

// ---------------- zero tail ----------------
__global__ void k_zerotail(float* __restrict__ p, int n) {
    int i = blockIdx.x*256 + threadIdx.x;
    int stride = gridDim.x*256;
    for (; i < n; i += stride) p[i] = 0.f;
}

// ---------------- init ----------------
__global__ void k_init(const float* __restrict__ candA) {
    int j = threadIdx.x;
    if (j < 4) g_acc[j] = 0.f;
    if (j == 4) {
        int all01 = 1;
        if (candA) {
            for (int i = 0; i < 256; i++) {
                float v = candA[i];
                if (v != 0.f && v != 1.f) { all01 = 0; break; }
            }
        } else all01 = 0;
        g_afirst_is_x = all01 ? 0 : 1;
    }
}

__global__ void k_initcn(const float* __restrict__ cb) {
    int j = blockIdx.x*256 + threadIdx.x;
    if (j < NE) {
        const float* c = cb + j*EE;
        float s = 0.f;
        for (int e = 0; e < EE; e++) { float v = c[e]; s += v*v; }
        g_cnorm[j] = s;
    }
}

// ---------------- encoder: 2 inst/block packed in f32x2 lanes -----------
// conv2: 16mt x 8nt, thread tile 4ch x 8l; 16-i weight chunks; h-vector
// double-buffer across i2 hides LDS latency.
__global__ __launch_bounds__(128, 3)
void k_encode(const float* __restrict__ candA, const float* __restrict__ candB,
              const float* __restrict__ imask,
              const float* __restrict__ w1g, const float* __restrict__ b1g,
              const float* __restrict__ w2g, const float* __restrict__ b2g,
              const float* __restrict__ latw, const float* __restrict__ latb)
{
    __shared__ __align__(16) u64 s_h1[64*54];   // 27.6 KB
    __shared__ __align__(16) u64 s_w2d[64*49];  // 25.1 KB: [o*49 + i2*3+k], 16-i chunk
    __shared__ u64 s_x[2*52];
    __shared__ u64 s_part[64*7];
    __shared__ u64 s_hbar[64];
    __shared__ float s_w1[384];
    __shared__ float s_b1[64], s_b2[64];

    const int tid = threadIdx.x;
    const int m0  = blockIdx.x * 2;
    const float im0 = __ldg(imask + m0), im1 = __ldg(imask + m0 + 1);

    // halos
    for (int idx = tid; idx < 256; idx += 128) {
        int row = idx >> 2, q = idx & 3;
        s_h1[row*54 + (q == 0 ? 0 : 50 + q)] = 0;   // idx 0, 51, 52, 53
    }
    if (tid < 4) s_x[(tid & 1)*52 + (tid >> 1)*51] = 0;
    for (int i = tid; i < 384; i += 128) s_w1[i] = w1g[i];
    if (tid < 64) { s_b1[tid] = b1g[tid]; s_b2[tid] = b2g[tid]; }

    // masked input pairs
    for (int t = tid; t < TT; t += 128) {
        float v0 = candA[(size_t)m0*TT + t]     * candB[(size_t)m0*TT + t]     * im0;
        float v1 = candA[(size_t)(m0+1)*TT + t] * candB[(size_t)(m0+1)*TT + t] * im1;
        s_x[(t & 1)*52 + 1 + (t >> 1)] = pk2(v0, v1);
    }
    __syncthreads();

    // conv1
    {
        const int o = tid & 63, lh = tid >> 6;
        const int lb = lh * 25;
        u64 wp[6];
        #pragma unroll
        for (int q = 0; q < 6; q++) { float w = s_w1[o*6 + q]; wp[q] = pk2(w, w); }
        float bs = s_b1[o];
        u64 bb = pk2(bs, bs);
        const u64* p0 = s_x;
        const u64* p1 = s_x + 52;
        u64* dst = s_h1 + o*54;
        #pragma unroll 5
        for (int l = lb; l < lb + 25; l++) {
            u64 v = bb;
            v = fma2(wp[0], p0[l],   v);
            v = fma2(wp[1], p0[l+1], v);
            v = fma2(wp[2], p0[l+2], v);
            v = fma2(wp[3], p1[l],   v);
            v = fma2(wp[4], p1[l+1], v);
            v = fma2(wp[5], p1[l+2], v);
            float a, b; upk2(v, a, b);
            dst[1 + l] = pk2(fmaxf(a, 0.f), fmaxf(b, 0.f));
        }
    }

    // conv2: 4 ch x 8 l per thread; double-buffered h vectors
    {
        const int mt = tid & 15;
        const int nt = tid >> 4;          // 0..7; active < 7
        const bool act = (nt < 7);
        const int lbase = nt * 8;

        u64 acc[4][8];
        #pragma unroll
        for (int oo = 0; oo < 4; oo++) {
            float bs = s_b2[mt + 16*oo];
            u64 bb = pk2(bs, bs);
            #pragma unroll
            for (int c = 0; c < 8; c++) acc[oo][c] = bb;
        }

        for (int chunk = 0; chunk < 4; chunk++) {
            __syncthreads();
            for (int idx = tid; idx < 64*48; idx += 128) {
                int o = idx / 48, r = idx - o*48;
                float wv = __ldg(w2g + o*192 + chunk*48 + r);
                s_w2d[o*49 + r] = pk2(wv, wv);
            }
            __syncthreads();
            if (act) {
                const u64* hbase = s_h1 + (chunk*16)*54 + lbase;
                ulonglong2 cA, cB, cC, cD, cE;
                {
                    const ulonglong2* hp = (const ulonglong2*)hbase;
                    cA = hp[0]; cB = hp[1]; cC = hp[2]; cD = hp[3]; cE = hp[4];
                }
                #pragma unroll
                for (int i2 = 0; i2 < 16; i2++) {
                    ulonglong2 nA, nB, nC, nD, nE;
                    if (i2 < 15) {
                        const ulonglong2* hp = (const ulonglong2*)(hbase + (i2 + 1)*54);
                        nA = hp[0]; nB = hp[1]; nC = hp[2]; nD = hp[3]; nE = hp[4];
                    }
                    u64 hv[10] = {cA.x, cA.y, cB.x, cB.y, cC.x, cC.y, cD.x, cD.y, cE.x, cE.y};
                    #pragma unroll
                    for (int k = 0; k < 3; k++) {
                        u64 w4[4];
                        #pragma unroll
                        for (int oo = 0; oo < 4; oo++)
                            w4[oo] = s_w2d[(mt + 16*oo)*49 + i2*3 + k];
                        #pragma unroll
                        for (int oo = 0; oo < 4; oo++) {
                            #pragma unroll
                            for (int c = 0; c < 8; c++)
                                acc[oo][c] = fma2(w4[oo], hv[c + k], acc[oo][c]);
                        }
                    }
                    if (i2 < 15) { cA = nA; cB = nB; cC = nC; cD = nD; cE = nE; }
                }
            }
        }

        if (act) {
            #pragma unroll
            for (int oo = 0; oo < 4; oo++) {
                float s0 = 0.f, s1 = 0.f;
                #pragma unroll
                for (int c = 0; c < 8; c++) {
                    if (lbase + c < 50) {
                        float a, b; upk2(acc[oo][c], a, b);
                        s0 += fmaxf(a, 0.f);
                        s1 += fmaxf(b, 0.f);
                    }
                }
                s_part[(mt + 16*oo)*7 + nt] = pk2(s0, s1);
            }
        }
    }
    __syncthreads();

    if (tid < 64) {
        float s0 = 0.f, s1 = 0.f;
        #pragma unroll 7
        for (int q = 0; q < 7; q++) {
            float a, b; upk2(s_part[tid*7 + q], a, b);
            s0 += a; s1 += b;
        }
        s_hbar[tid] = pk2(s0 * (1.f/50.f), s1 * (1.f/50.f));
    }
    __syncthreads();

    // latent
    {
        const int e = tid;
        const float4* lw4 = (const float4*)(latw + e*64);
        u64 acc = 0;
        #pragma unroll 4
        for (int c4 = 0; c4 < 16; c4++) {
            float4 wv = __ldg(lw4 + c4);
            acc = fma2(pk2(wv.x, wv.x), s_hbar[c4*4 + 0], acc);
            acc = fma2(pk2(wv.y, wv.y), s_hbar[c4*4 + 1], acc);
            acc = fma2(pk2(wv.z, wv.z), s_hbar[c4*4 + 2], acc);
            acc = fma2(pk2(wv.w, wv.w), s_hbar[c4*4 + 3], acc);
        }
        float z0, z1; upk2(acc, z0, z1);
        float bb = __ldg(latb + e);
        g_z[(size_t)m0*EE + e]       = (z0 + bb) * im0;
        g_z[(size_t)(m0 + 1)*EE + e] = (z1 + bb) * im1;
    }
}

// ---------------- VQ (R6 version, ~256us) ----------------
__device__ __forceinline__ unsigned fkey(float f) {
    unsigned u = __float_as_uint(f);
    return (u & 0x80000000u) ? ~u : (u | 0x80000000u);
}

__global__ __launch_bounds__(256)
void k_vq(const float* __restrict__ cb, const float* __restrict__ imask,
          float* __restrict__ outp, int out_size)
{
    __shared__ __align__(16) float s_z[64*128];
    __shared__ __align__(16) float s_c[64*130];
    __shared__ float s_cn[64], s_zn[64], s_imv[64];
    __shared__ u64   s_best[64];

    const int tid = threadIdx.x;
    const int m0  = blockIdx.x * 64;

    for (int i = tid; i < 64*128; i += 256) s_z[i] = g_z[(size_t)m0*128 + i];
    if (tid < 64) { s_best[tid] = 0xFFFFFFFFFFFFFFFFull; s_imv[tid] = imask[m0 + tid]; }
    __syncthreads();
    if (tid < 64) {
        const float* z = s_z + tid*128;
        float s = 0.f;
        for (int e = 0; e < 128; e++) s += z[e]*z[e];
        s_zn[tid] = s;
    }

    const int cq = tid & 15;
    const int zq = tid >> 4;

    float bd[4]; int bj[4];
    #pragma unroll
    for (int r = 0; r < 4; r++) { bd[r] = 3.4e38f; bj[r] = 0; }

    const u64* zp[4];
    #pragma unroll
    for (int r = 0; r < 4; r++) zp[r] = (const u64*)(s_z + (zq + 16*r)*128);

    for (int tile = 0; tile < 8; tile++) {
        __syncthreads();
        for (int i = tid; i < 64*128; i += 256) {
            int row = i >> 7, e = i & 127;
            s_c[row*130 + e] = cb[(size_t)(tile*64 + row)*128 + e];
        }
        if (tid < 64) s_cn[tid] = g_cnorm[tile*64 + tid];
        __syncthreads();

        u64 dt[4][4];
        #pragma unroll
        for (int r = 0; r < 4; r++)
            #pragma unroll
            for (int q = 0; q < 4; q++) dt[r][q] = 0;

        const u64* cp[4];
        #pragma unroll
        for (int q = 0; q < 4; q++) cp[q] = (const u64*)(s_c + (cq + 16*q)*130);

        #pragma unroll 2
        for (int e2 = 0; e2 < 64; e2++) {
            u64 zv0 = zp[0][e2], zv1 = zp[1][e2], zv2 = zp[2][e2], zv3 = zp[3][e2];
            u64 cv0 = cp[0][e2], cv1 = cp[1][e2], cv2 = cp[2][e2], cv3 = cp[3][e2];
            dt[0][0] = fma2(zv0, cv0, dt[0][0]); dt[0][1] = fma2(zv0, cv1, dt[0][1]);
            dt[0][2] = fma2(zv0, cv2, dt[0][2]); dt[0][3] = fma2(zv0, cv3, dt[0][3]);
            dt[1][0] = fma2(zv1, cv0, dt[1][0]); dt[1][1] = fma2(zv1, cv1, dt[1][1]);
            dt[1][2] = fma2(zv1, cv2, dt[1][2]); dt[1][3] = fma2(zv1, cv3, dt[1][3]);
            dt[2][0] = fma2(zv2, cv0, dt[2][0]); dt[2][1] = fma2(zv2, cv1, dt[2][1]);
            dt[2][2] = fma2(zv2, cv2, dt[2][2]); dt[2][3] = fma2(zv2, cv3, dt[2][3]);
            dt[3][0] = fma2(zv3, cv0, dt[3][0]); dt[3][1] = fma2(zv3, cv1, dt[3][1]);
            dt[3][2] = fma2(zv3, cv2, dt[3][2]); dt[3][3] = fma2(zv3, cv3, dt[3][3]);
        }

        #pragma unroll
        for (int q = 0; q < 4; q++) {
            float cn = s_cn[cq + 16*q];
            int j = tile*64 + cq + 16*q;
            #pragma unroll
            for (int r = 0; r < 4; r++) {
                float lo, hi; upk2(dt[r][q], lo, hi);
                float d = (s_zn[zq + 16*r] - 2.f*(lo + hi)) + cn;
                if (d < bd[r]) { bd[r] = d; bj[r] = j; }
            }
        }
    }
    #pragma unroll
    for (int r = 0; r < 4; r++) {
        u64 pkv = ((u64)fkey(bd[r]) << 32) | (unsigned)bj[r];
        atomicMin(&s_best[zq + 16*r], pkv);
    }
    __syncthreads();

    if (tid < 64) {
        int j = (int)(s_best[tid] & 0xFFFFFFFFu);
        g_idx[m0 + tid] = j;
        float imv = s_imv[tid];
        if (out_size >= OFF_IDX + MTOT)
            outp[OFF_IDX + m0 + tid] = (imv > 0.f) ? (float)j : -1.f;
        float v = imv;
        #pragma unroll
        for (int off = 16; off; off >>= 1) v += __shfl_down_sync(0xffffffffu, v, off);
        if ((tid & 31) == 0) atomicAdd(&g_acc[3], v);
    }

    {
        int is = tid >> 2, q = tid & 3;
        int j = (int)(s_best[is] & 0xFFFFFFFFu) & (NE - 1);
        const float* c = cb + (size_t)j*128;
        const float* z = s_z + is*128;
        float s = 0.f;
        for (int e = q*32; e < q*32 + 32; e++) { float d = z[e] - c[e]; s += d*d; }
        s += __shfl_down_sync(0xffffffffu, s, 2, 4);
        s += __shfl_down_sync(0xffffffffu, s, 1, 4);
        if (q == 0) atomicAdd(&g_acc[2], s * ((1.f + BETA)/128.f) * s_imv[is]);
    }
}

// ---------------- decoder: 16 inst/block, 4 blocks/SM -------------------
#define APF 264
#define WPU 265

template<int KHALF, int SGRP>
__device__ __forceinline__ void dec_mm(const float* __restrict__ W, int NOUT,
        const float* sX, u64* sW2, u64 (&acc)[4][8], int tx, int ig, int tid)
{
    #pragma unroll
    for (int i = 0; i < 4; i++)
        #pragma unroll
        for (int s = 0; s < SGRP; s++) acc[i][s] = 0;
    const u64* Wu = (const u64*)W;
    const u64* aX = (const u64*)sX;
    for (int kc = 0; kc < KHALF; kc += 8) {
        __syncthreads();
        for (int idx = tid; idx < 256*8; idx += 128) {
            int row = idx >> 3, r = idx & 7;
            u64 v = 0;
            if (row < NOUT) v = __ldg(Wu + (size_t)row*KHALF + kc + r);
            sW2[r*WPU + row] = v;
        }
        __syncthreads();
        #pragma unroll
        for (int kp = 0; kp < 8; kp++) {
            u64 a4[4], w8[8];
            #pragma unroll
            for (int i = 0; i < 4; i++) a4[i] = aX[(ig*4 + i)*(APF/2) + kc + kp];
            #pragma unroll
            for (int s = 0; s < SGRP; s++) w8[s] = sW2[kp*WPU + tx + 32*s];
            #pragma unroll
            for (int i = 0; i < 4; i++)
                #pragma unroll
                for (int s = 0; s < SGRP; s++)
                    acc[i][s] = fma2(w8[s], a4[i], acc[i][s]);
        }
    }
}

__global__ __launch_bounds__(128, 4)
void k_dec(const float* __restrict__ cb, const float* __restrict__ imask,
           const float* __restrict__ d1w, const float* __restrict__ d1b,
           const float* __restrict__ d2w, const float* __restrict__ d2b,
           const float* __restrict__ d3w, const float* __restrict__ d3b,
           const float* __restrict__ candA, const float* __restrict__ candB,
           float* __restrict__ outp)
{
    __shared__ __align__(16) float sA[16*APF];   // 16.9 KB
    __shared__ __align__(16) float sB[16*APF];   // 16.9 KB
    __shared__ u64 sW2[8*WPU];                   // 17.0 KB
    __shared__ float s_im[16];
    __shared__ int   s_j[16];

    const int tid = threadIdx.x;
    const int tx  = tid & 31;
    const int ig  = tid >> 5;        // warp -> 4 instances
    const int m0  = blockIdx.x * 16;

    if (tid < 16) { s_im[tid] = imask[m0 + tid]; s_j[tid] = g_idx[m0 + tid] & (NE - 1); }
    __syncthreads();

    for (int i = tid; i < 16*128; i += 128) {
        int ii = i >> 7, e = i & 127;
        sA[ii*APF + e] = cb[(size_t)s_j[ii]*128 + e] * s_im[ii];
    }

    u64 acc[4][8];

    dec_mm<64, 8>(d1w, 256, sA, sW2, acc, tx, ig, tid);
    __syncthreads();
    #pragma unroll
    for (int s = 0; s < 8; s++) {
        int o = tx + 32*s;
        float bb = __ldg(d1b + o);
        #pragma unroll
        for (int i = 0; i < 4; i++) {
            float lo, hi; upk2(acc[i][s], lo, hi);
            sB[(ig*4 + i)*APF + o] = fmaxf(lo + hi + bb, 0.f);
        }
    }

    dec_mm<128, 8>(d2w, 256, sB, sW2, acc, tx, ig, tid);
    __syncthreads();
    #pragma unroll
    for (int s = 0; s < 8; s++) {
        int o = tx + 32*s;
        float bb = __ldg(d2b + o);
        #pragma unroll
        for (int i = 0; i < 4; i++) {
            float lo, hi; upk2(acc[i][s], lo, hi);
            sA[(ig*4 + i)*APF + o] = fmaxf(lo + hi + bb, 0.f);
        }
    }

    dec_mm<128, 4>(d3w, 100, sA, sW2, acc, tx, ig, tid);
    {
        const float* xr = candA; const float* tmr = candB;
        if (g_afirst_is_x == 0) { xr = candB; tmr = candA; }

        float rsum = 0.f, wsum = 0.f;
        #pragma unroll
        for (int s = 0; s < 4; s++) {
            int o = tx + 32*s;
            if (o < TT) {
                float bb = __ldg(d3b + o);
                #pragma unroll
                for (int i = 0; i < 4; i++) {
                    int m = m0 + ig*4 + i;
                    float lo, hi; upk2(acc[i][s], lo, hi);
                    float v = lo + hi + bb;
                    outp[(size_t)m*TT + o] = v;
                    float wgt = s_im[ig*4 + i] * tmr[(size_t)m*TT + o];
                    float d = v - xr[(size_t)m*TT + o];
                    rsum += d*d*wgt; wsum += wgt;
                }
            }
        }
        #pragma unroll
        for (int off = 16; off; off >>= 1) {
            rsum += __shfl_down_sync(0xffffffffu, rsum, off);
            wsum += __shfl_down_sync(0xffffffffu, wsum, off);
        }
        if ((tid & 31) == 0) {
            atomicAdd(&g_acc[0], rsum);
            atomicAdd(&g_acc[1], wsum);
        }
    }
}

// ---------------- finalize ----------------
__global__ void k_final(float* __restrict__ outp, int out_size) {
    if (out_size > OFF_VQ) {
        outp[OFF_RECON] = g_acc[0] / fmaxf(g_acc[1], 1.f);
        outp[OFF_VQ]    = g_acc[2] / fmaxf(g_acc[3], 1.f);
    }
}

// ---------------- launch ----------------
extern "C" void kernel_launch(void* const* d_in, const int* in_sizes, int n_in,
                              void* d_out, int out_size)
{
    const float *candA=0,*candB=0,*im=0,*c1w=0,*c1b=0,*c2w=0,*c2b=0;
    const float *latw=0,*latb=0,*cb=0,*d1w=0,*d1b=0,*d2w=0,*d2b=0,*d3w=0,*d3b=0;

    int scale = 1;
    for (int i = 0; i < n_in; i++)
        if (in_sizes[i] == 5120000*4) { scale = 4; break; }

    int c5=0,c64=0,c256=0,c65k=0;
    for (int i = 0; i < n_in; i++) {
        const float* p = (const float*)d_in[i];
        int sz = in_sizes[i] / scale;
        switch (sz) {
            case 5120000: if (c5++ == 0) candA = p; else candB = p; break;
            case 51200:   im   = p; break;
            case 384:     c1w  = p; break;
            case 64:      if (c64++ == 0) c1b = p; else c2b = p; break;
            case 12288:   c2w  = p; break;
            case 8192:    latw = p; break;
            case 128:     latb = p; break;
            case 65536:   if (c65k++ == 0) cb = p; else d2w = p; break;
            case 32768:   d1w  = p; break;
            case 256:     if (c256++ == 0) d1b = p; else d2b = p; break;
            case 25600:   d3w  = p; break;
            case 100:     d3b  = p; break;
            default: break;
        }
    }
    if ((!candA || !candB || !im || !cb || !d1w || !d2w || !d3w) && n_in >= 16) {
        candA = (const float*)d_in[0];  candB = (const float*)d_in[1];
        im    = (const float*)d_in[2];
        c1w   = (const float*)d_in[3];  c1b   = (const float*)d_in[4];
        c2w   = (const float*)d_in[5];  c2b   = (const float*)d_in[6];
        latw  = (const float*)d_in[7];  latb  = (const float*)d_in[8];
        cb    = (const float*)d_in[9];
        d1w   = (const float*)d_in[10]; d1b   = (const float*)d_in[11];
        d2w   = (const float*)d_in[12]; d2b   = (const float*)d_in[13];
        d3w   = (const float*)d_in[14]; d3b   = (const float*)d_in[15];
    }
    if (!candB) candB = candA;

    float* outp = (float*)d_out;

    k_zerotail<<<32, 256>>>(outp + XH_ELEMS, out_size > XH_ELEMS ? out_size - XH_ELEMS : 0);  // 1
    k_init<<<1, 32>>>(candA);                                                                  // 2
    k_initcn<<<2, 256>>>(cb);                                                                  // 3
    k_encode<<<MTOT/2, 128>>>(candA, candB, im, c1w, c1b, c2w, c2b, latw, latb);               // 4 (profiled)
    k_vq<<<MTOT/64, 256>>>(cb, im, outp, out_size);                                            // 5
    k_dec<<<MTOT/16, 128>>>(cb, im, d1w, d1b, d2w, d2b, d3w, d3b, candA, candB, outp);         // 6
    k_final<<<1, 1>>>(outp, out_size);                                                         // 7
}

// round 13
// speedup vs baseline: 1.0673x; 1.0673x over previous
#include <cuda_runtime.h>
#include <math.h>

// ---------------- problem constants ----------------
#define MB      512
#define NN      100
#define TT      100
#define LL      50
#define HE      64
#define EE      128
#define NE      512
#define HD      256
#define MTOT    (MB*NN)     // 51200
#define BETA    0.25f

#define XH_ELEMS   (MTOT*TT)        // 5,120,000
#define OFF_RECON  (XH_ELEMS)
#define OFF_VQ     (XH_ELEMS+1)
#define OFF_IDX    (XH_ELEMS+2)

typedef unsigned long long u64;

// ---- f32x2 helpers ----
__device__ __forceinline__ u64 pk2(float lo, float hi) {
    u64 r;
    asm("mov.b64 %0, {%1, %2};" : "=l"(r) : "r"(__float_as_uint(lo)), "r"(__float_as_uint(hi)));
    return r;
}
__device__ __forceinline__ void upk2(u64 v, float& lo, float& hi) {
    unsigned a, b;
    asm("mov.b64 {%0, %1}, %2;" : "=r"(a), "=r"(b) : "l"(v));
    lo = __uint_as_float(a); hi = __uint_as_float(b);
}
__device__ __forceinline__ u64 fma2(u64 a, u64 b, u64 c) {
    u64 d;
    asm("fma.rn.f32x2 %0, %1, %2, %3;" : "=l"(d) : "l"(a), "l"(b), "l"(c));
    return d;
}

// ---------------- device scratch ----------------
__device__ float g_z[MTOT*EE];
__device__ int   g_idx[MTOT];
__device__ float g_cnorm[NE];
__device__ float g_acc[4];
__device__ int   g_afirst_is_x;

// ---------------- zero tail ----------------
__global__ void k_zerotail(float* __restrict__ p, int n) {
    int i = blockIdx.x*256 + threadIdx.x;
    int stride = gridDim.x*256;
    for (; i < n; i += stride) p[i] = 0.f;
}

// ---------------- init ----------------
__global__ void k_init(const float* __restrict__ candA) {
    int j = threadIdx.x;
    if (j < 4) g_acc[j] = 0.f;
    if (j == 4) {
        int all01 = 1;
        if (candA) {
            for (int i = 0; i < 256; i++) {
                float v = candA[i];
                if (v != 0.f && v != 1.f) { all01 = 0; break; }
            }
        } else all01 = 0;
        g_afirst_is_x = all01 ? 0 : 1;
    }
}

__global__ void k_initcn(const float* __restrict__ cb) {
    int j = blockIdx.x*256 + threadIdx.x;
    if (j < NE) {
        const float* c = cb + j*EE;
        float s = 0.f;
        for (int e = 0; e < EE; e++) { float v = c[e]; s += v*v; }
        g_cnorm[j] = s;
    }
}

// ---------------- encoder (R11 version — best known) --------------------
__global__ __launch_bounds__(128, 4)
void k_encode(const float* __restrict__ candA, const float* __restrict__ candB,
              const float* __restrict__ imask,
              const float* __restrict__ w1g, const float* __restrict__ b1g,
              const float* __restrict__ w2g, const float* __restrict__ b2g,
              const float* __restrict__ latw, const float* __restrict__ latb)
{
    __shared__ __align__(16) u64 s_h1[64*54];   // 27.6 KB
    __shared__ __align__(16) u64 s_w2d[64*25];  // 12.8 KB: [o*25 + i2*3+k], 8-i chunk
    __shared__ u64 s_x[2*52];
    __shared__ u64 s_part[64*7];
    __shared__ u64 s_hbar[64];
    __shared__ float s_w1[384];
    __shared__ float s_b1[64], s_b2[64];

    const int tid = threadIdx.x;
    const int m0  = blockIdx.x * 2;
    const float im0 = __ldg(imask + m0), im1 = __ldg(imask + m0 + 1);

    // halos
    for (int idx = tid; idx < 256; idx += 128) {
        int row = idx >> 2, q = idx & 3;
        s_h1[row*54 + (q == 0 ? 0 : 50 + q)] = 0;   // idx 0, 51, 52, 53
    }
    if (tid < 4) s_x[(tid & 1)*52 + (tid >> 1)*51] = 0;
    for (int i = tid; i < 384; i += 128) s_w1[i] = w1g[i];
    if (tid < 64) { s_b1[tid] = b1g[tid]; s_b2[tid] = b2g[tid]; }

    // masked input pairs
    for (int t = tid; t < TT; t += 128) {
        float v0 = candA[(size_t)m0*TT + t]     * candB[(size_t)m0*TT + t]     * im0;
        float v1 = candA[(size_t)(m0+1)*TT + t] * candB[(size_t)(m0+1)*TT + t] * im1;
        s_x[(t & 1)*52 + 1 + (t >> 1)] = pk2(v0, v1);
    }
    __syncthreads();

    // conv1: thread = (lhalf, o), 25 l's, instance-pair f32x2
    {
        const int o = tid & 63, lh = tid >> 6;
        const int lb = lh * 25;
        u64 wp[6];
        #pragma unroll
        for (int q = 0; q < 6; q++) { float w = s_w1[o*6 + q]; wp[q] = pk2(w, w); }
        float bs = s_b1[o];
        u64 bb = pk2(bs, bs);
        const u64* p0 = s_x;
        const u64* p1 = s_x + 52;
        u64* dst = s_h1 + o*54;
        #pragma unroll 5
        for (int l = lb; l < lb + 25; l++) {
            u64 v = bb;
            v = fma2(wp[0], p0[l],   v);
            v = fma2(wp[1], p0[l+1], v);
            v = fma2(wp[2], p0[l+2], v);
            v = fma2(wp[3], p1[l],   v);
            v = fma2(wp[4], p1[l+1], v);
            v = fma2(wp[5], p1[l+2], v);
            float a, b; upk2(v, a, b);
            dst[1 + l] = pk2(fmaxf(a, 0.f), fmaxf(b, 0.f));
        }
    }

    // conv2: thread tile 4 channel-pairs (o = mt + 16*oo) x 8 l (lbase = nt*8)
    {
        const int mt = tid & 15;
        const int nt = tid >> 4;          // 0..7; active < 7
        const bool act = (nt < 7);
        const int lbase = nt * 8;

        u64 acc[4][8];
        #pragma unroll
        for (int oo = 0; oo < 4; oo++) {
            float bs = s_b2[mt + 16*oo];
            u64 bb = pk2(bs, bs);
            #pragma unroll
            for (int c = 0; c < 8; c++) acc[oo][c] = bb;
        }

        for (int chunk = 0; chunk < 8; chunk++) {
            __syncthreads();
            for (int idx = tid; idx < 64*24; idx += 128) {
                int o = idx / 24, r = idx - o*24;
                float wv = __ldg(w2g + o*192 + chunk*24 + r);
                s_w2d[o*25 + r] = pk2(wv, wv);
            }
            __syncthreads();
            if (act) {
                #pragma unroll
                for (int i2 = 0; i2 < 8; i2++) {
                    const int i = chunk*8 + i2;
                    const ulonglong2* hp = (const ulonglong2*)(s_h1 + i*54 + lbase);
                    ulonglong2 hA = hp[0], hB = hp[1], hC = hp[2], hD = hp[3], hE = hp[4];
                    u64 hv[10] = {hA.x, hA.y, hB.x, hB.y, hC.x, hC.y, hD.x, hD.y, hE.x, hE.y};
                    #pragma unroll
                    for (int k = 0; k < 3; k++) {
                        u64 w4[4];
                        #pragma unroll
                        for (int oo = 0; oo < 4; oo++)
                            w4[oo] = s_w2d[(mt + 16*oo)*25 + i2*3 + k];
                        #pragma unroll
                        for (int oo = 0; oo < 4; oo++) {
                            #pragma unroll
                            for (int c = 0; c < 8; c++)
                                acc[oo][c] = fma2(w4[oo], hv[c + k], acc[oo][c]);
                        }
                    }
                }
            }
        }

        if (act) {
            #pragma unroll
            for (int oo = 0; oo < 4; oo++) {
                float s0 = 0.f, s1 = 0.f;
                #pragma unroll
                for (int c = 0; c < 8; c++) {
                    if (lbase + c < 50) {
                        float a, b; upk2(acc[oo][c], a, b);
                        s0 += fmaxf(a, 0.f);
                        s1 += fmaxf(b, 0.f);
                    }
                }
                s_part[(mt + 16*oo)*7 + nt] = pk2(s0, s1);
            }
        }
    }
    __syncthreads();

    if (tid < 64) {
        float s0 = 0.f, s1 = 0.f;
        #pragma unroll 7
        for (int q = 0; q < 7; q++) {
            float a, b; upk2(s_part[tid*7 + q], a, b);
            s0 += a; s1 += b;
        }
        s_hbar[tid] = pk2(s0 * (1.f/50.f), s1 * (1.f/50.f));
    }
    __syncthreads();

    // latent: thread = e (128 outputs), both instances at once
    {
        const int e = tid;
        const float4* lw4 = (const float4*)(latw + e*64);
        u64 acc = 0;
        #pragma unroll 4
        for (int c4 = 0; c4 < 16; c4++) {
            float4 wv = __ldg(lw4 + c4);
            acc = fma2(pk2(wv.x, wv.x), s_hbar[c4*4 + 0], acc);
            acc = fma2(pk2(wv.y, wv.y), s_hbar[c4*4 + 1], acc);
            acc = fma2(pk2(wv.z, wv.z), s_hbar[c4*4 + 2], acc);
            acc = fma2(pk2(wv.w, wv.w), s_hbar[c4*4 + 3], acc);
        }
        float z0, z1; upk2(acc, z0, z1);
        float bb = __ldg(latb + e);
        g_z[(size_t)m0*EE + e]       = (z0 + bb) * im0;
        g_z[(size_t)(m0 + 1)*EE + e] = (z1 + bb) * im1;
    }
}

// ---------------- VQ: 128 threads, 8z x 4c register tile ----------------
__device__ __forceinline__ unsigned fkey(float f) {
    unsigned u = __float_as_uint(f);
    return (u & 0x80000000u) ? ~u : (u | 0x80000000u);
}

__global__ __launch_bounds__(128)
void k_vq(const float* __restrict__ cb, const float* __restrict__ imask,
          float* __restrict__ outp, int out_size)
{
    __shared__ __align__(16) float s_z[64*128];     // 32 KB
    __shared__ __align__(16) float s_c[64*130];     // 33.3 KB
    __shared__ float s_cn[64], s_zn[64], s_imv[64];
    __shared__ u64   s_best[64];

    const int tid = threadIdx.x;
    const int m0  = blockIdx.x * 64;

    for (int i = tid; i < 64*128; i += 128) s_z[i] = g_z[(size_t)m0*128 + i];
    if (tid < 64) { s_best[tid] = 0xFFFFFFFFFFFFFFFFull; s_imv[tid] = imask[m0 + tid]; }
    __syncthreads();
    if (tid < 64) {
        const float* z = s_z + tid*128;
        float s = 0.f;
        for (int e = 0; e < 128; e++) s += z[e]*z[e];
        s_zn[tid] = s;
    }

    const int cq = tid & 15;        // codes cq + 16q, q<4
    const int zq = tid >> 4;        // z rows zq + 8r, r<8 (zq in 0..7)

    float bd[8]; int bj[8];
    #pragma unroll
    for (int r = 0; r < 8; r++) { bd[r] = 3.4e38f; bj[r] = 0; }

    const u64* zp[8];
    #pragma unroll
    for (int r = 0; r < 8; r++) zp[r] = (const u64*)(s_z + (zq + 8*r)*128);

    for (int tile = 0; tile < 8; tile++) {
        __syncthreads();
        for (int i = tid; i < 64*128; i += 128) {
            int row = i >> 7, e = i & 127;
            s_c[row*130 + e] = cb[(size_t)(tile*64 + row)*128 + e];
        }
        if (tid < 64) s_cn[tid] = g_cnorm[tile*64 + tid];
        __syncthreads();

        u64 dt[8][4];
        #pragma unroll
        for (int r = 0; r < 8; r++)
            #pragma unroll
            for (int q = 0; q < 4; q++) dt[r][q] = 0;

        const u64* cp[4];
        #pragma unroll
        for (int q = 0; q < 4; q++) cp[q] = (const u64*)(s_c + (cq + 16*q)*130);

        for (int e2 = 0; e2 < 64; e2++) {
            u64 cv0 = cp[0][e2], cv1 = cp[1][e2], cv2 = cp[2][e2], cv3 = cp[3][e2];
            #pragma unroll
            for (int r = 0; r < 8; r++) {
                u64 zv = zp[r][e2];
                dt[r][0] = fma2(zv, cv0, dt[r][0]);
                dt[r][1] = fma2(zv, cv1, dt[r][1]);
                dt[r][2] = fma2(zv, cv2, dt[r][2]);
                dt[r][3] = fma2(zv, cv3, dt[r][3]);
            }
        }

        #pragma unroll
        for (int q = 0; q < 4; q++) {
            float cn = s_cn[cq + 16*q];
            int j = tile*64 + cq + 16*q;
            #pragma unroll
            for (int r = 0; r < 8; r++) {
                float lo, hi; upk2(dt[r][q], lo, hi);
                float d = (s_zn[zq + 8*r] - 2.f*(lo + hi)) + cn;
                if (d < bd[r]) { bd[r] = d; bj[r] = j; }
            }
        }
    }
    #pragma unroll
    for (int r = 0; r < 8; r++) {
        u64 pkv = ((u64)fkey(bd[r]) << 32) | (unsigned)bj[r];
        atomicMin(&s_best[zq + 8*r], pkv);
    }
    __syncthreads();

    if (tid < 64) {
        int j = (int)(s_best[tid] & 0xFFFFFFFFu);
        g_idx[m0 + tid] = j;
        float imv = s_imv[tid];
        if (out_size >= OFF_IDX + MTOT)
            outp[OFF_IDX + m0 + tid] = (imv > 0.f) ? (float)j : -1.f;
        float v = imv;
        #pragma unroll
        for (int off = 16; off; off >>= 1) v += __shfl_down_sync(0xffffffffu, v, off);
        if ((tid & 31) == 0) atomicAdd(&g_acc[3], v);
    }

    // vq loss: (1+BETA) * mean((z - c)^2) * im; 2 threads per instance
    {
        int is = tid >> 1, half = tid & 1;
        int j = (int)(s_best[is] & 0xFFFFFFFFu) & (NE - 1);
        const float* c = cb + (size_t)j*128;
        const float* z = s_z + is*128;
        float s = 0.f;
        for (int e = half*64; e < half*64 + 64; e++) { float d = z[e] - c[e]; s += d*d; }
        s += __shfl_down_sync(0xffffffffu, s, 1, 2);
        if (half == 0) atomicAdd(&g_acc[2], s * ((1.f + BETA)/128.f) * s_imv[is]);
    }
}

// ---------------- decoder (R7 version — best known) ----------------
#define APF 264
#define WPU 265

template<int KHALF, int SGRP>
__device__ __forceinline__ void dec_mm(const float* __restrict__ W, int NOUT,
        const float* sX, u64* sW2, u64 (&acc)[8][8], int tx, int ig, int tid)
{
    #pragma unroll
    for (int i = 0; i < 8; i++)
        #pragma unroll
        for (int s = 0; s < SGRP; s++) acc[i][s] = 0;
    const u64* Wu = (const u64*)W;
    const u64* aX = (const u64*)sX;
    for (int kc = 0; kc < KHALF; kc += 8) {
        __syncthreads();
        for (int idx = tid; idx < 256*8; idx += 128) {
            int row = idx >> 3, r = idx & 7;
            u64 v = 0;
            if (row < NOUT) v = __ldg(Wu + (size_t)row*KHALF + kc + r);
            sW2[r*WPU + row] = v;
        }
        __syncthreads();
        #pragma unroll
        for (int kp = 0; kp < 8; kp++) {
            u64 a8[8], w8[8];
            #pragma unroll
            for (int i = 0; i < 8; i++) a8[i] = aX[(ig*8 + i)*(APF/2) + kc + kp];
            #pragma unroll
            for (int s = 0; s < SGRP; s++) w8[s] = sW2[kp*WPU + tx + 32*s];
            #pragma unroll
            for (int i = 0; i < 8; i++)
                #pragma unroll
                for (int s = 0; s < SGRP; s++)
                    acc[i][s] = fma2(w8[s], a8[i], acc[i][s]);
        }
    }
}

__global__ __launch_bounds__(128, 2)
void k_dec(const float* __restrict__ cb, const float* __restrict__ imask,
           const float* __restrict__ d1w, const float* __restrict__ d1b,
           const float* __restrict__ d2w, const float* __restrict__ d2b,
           const float* __restrict__ d3w, const float* __restrict__ d3b,
           const float* __restrict__ candA, const float* __restrict__ candB,
           float* __restrict__ outp)
{
    __shared__ __align__(16) float sA[32*APF];
    __shared__ __align__(16) float sB[32*APF];
    __shared__ u64 sW2[8*WPU];
    __shared__ float s_im[32];
    __shared__ int   s_j[32];

    const int tid = threadIdx.x;
    const int tx  = tid & 31;
    const int ig  = tid >> 5;
    const int m0  = blockIdx.x * 32;

    if (tid < 32) { s_im[tid] = imask[m0 + tid]; s_j[tid] = g_idx[m0 + tid] & (NE - 1); }
    __syncthreads();

    for (int i = tid; i < 32*128; i += 128) {
        int ii = i >> 7, e = i & 127;
        sA[ii*APF + e] = cb[(size_t)s_j[ii]*128 + e] * s_im[ii];
    }

    u64 acc[8][8];

    dec_mm<64, 8>(d1w, 256, sA, sW2, acc, tx, ig, tid);
    __syncthreads();
    #pragma unroll
    for (int s = 0; s < 8; s++) {
        int o = tx + 32*s;
        float bb = __ldg(d1b + o);
        #pragma unroll
        for (int i = 0; i < 8; i++) {
            float lo, hi; upk2(acc[i][s], lo, hi);
            sB[(ig*8 + i)*APF + o] = fmaxf(lo + hi + bb, 0.f);
        }
    }

    dec_mm<128, 8>(d2w, 256, sB, sW2, acc, tx, ig, tid);
    __syncthreads();
    #pragma unroll
    for (int s = 0; s < 8; s++) {
        int o = tx + 32*s;
        float bb = __ldg(d2b + o);
        #pragma unroll
        for (int i = 0; i < 8; i++) {
            float lo, hi; upk2(acc[i][s], lo, hi);
            sA[(ig*8 + i)*APF + o] = fmaxf(lo + hi + bb, 0.f);
        }
    }

    dec_mm<128, 4>(d3w, 100, sA, sW2, acc, tx, ig, tid);
    {
        const float* xr = candA; const float* tmr = candB;
        if (g_afirst_is_x == 0) { xr = candB; tmr = candA; }

        float rsum = 0.f, wsum = 0.f;
        #pragma unroll
        for (int s = 0; s < 4; s++) {
            int o = tx + 32*s;
            if (o < TT) {
                float bb = __ldg(d3b + o);
                #pragma unroll
                for (int i = 0; i < 8; i++) {
                    int m = m0 + ig*8 + i;
                    float lo, hi; upk2(acc[i][s], lo, hi);
                    float v = lo + hi + bb;
                    outp[(size_t)m*TT + o] = v;
                    float wgt = s_im[ig*8 + i] * tmr[(size_t)m*TT + o];
                    float d = v - xr[(size_t)m*TT + o];
                    rsum += d*d*wgt; wsum += wgt;
                }
            }
        }
        #pragma unroll
        for (int off = 16; off; off >>= 1) {
            rsum += __shfl_down_sync(0xffffffffu, rsum, off);
            wsum += __shfl_down_sync(0xffffffffu, wsum, off);
        }
        if ((tid & 31) == 0) {
            atomicAdd(&g_acc[0], rsum);
            atomicAdd(&g_acc[1], wsum);
        }
    }
}

// ---------------- finalize ----------------
__global__ void k_final(float* __restrict__ outp, int out_size) {
    if (out_size > OFF_VQ) {
        outp[OFF_RECON] = g_acc[0] / fmaxf(g_acc[1], 1.f);
        outp[OFF_VQ]    = g_acc[2] / fmaxf(g_acc[3], 1.f);
    }
}

// ---------------- launch ----------------
extern "C" void kernel_launch(void* const* d_in, const int* in_sizes, int n_in,
                              void* d_out, int out_size)
{
    const float *candA=0,*candB=0,*im=0,*c1w=0,*c1b=0,*c2w=0,*c2b=0;
    const float *latw=0,*latb=0,*cb=0,*d1w=0,*d1b=0,*d2w=0,*d2b=0,*d3w=0,*d3b=0;

    int scale = 1;
    for (int i = 0; i < n_in; i++)
        if (in_sizes[i] == 5120000*4) { scale = 4; break; }

    int c5=0,c64=0,c256=0,c65k=0;
    for (int i = 0; i < n_in; i++) {
        const float* p = (const float*)d_in[i];
        int sz = in_sizes[i] / scale;
        switch (sz) {
            case 5120000: if (c5++ == 0) candA = p; else candB = p; break;
            case 51200:   im   = p; break;
            case 384:     c1w  = p; break;
            case 64:      if (c64++ == 0) c1b = p; else c2b = p; break;
            case 12288:   c2w  = p; break;
            case 8192:    latw = p; break;
            case 128:     latb = p; break;
            case 65536:   if (c65k++ == 0) cb = p; else d2w = p; break;
            case 32768:   d1w  = p; break;
            case 256:     if (c256++ == 0) d1b = p; else d2b = p; break;
            case 25600:   d3w  = p; break;
            case 100:     d3b  = p; break;
            default: break;
        }
    }
    if ((!candA || !candB || !im || !cb || !d1w || !d2w || !d3w) && n_in >= 16) {
        candA = (const float*)d_in[0];  candB = (const float*)d_in[1];
        im    = (const float*)d_in[2];
        c1w   = (const float*)d_in[3];  c1b   = (const float*)d_in[4];
        c2w   = (const float*)d_in[5];  c2b   = (const float*)d_in[6];
        latw  = (const float*)d_in[7];  latb  = (const float*)d_in[8];
        cb    = (const float*)d_in[9];
        d1w   = (const float*)d_in[10]; d1b   = (const float*)d_in[11];
        d2w   = (const float*)d_in[12]; d2b   = (const float*)d_in[13];
        d3w   = (const float*)d_in[14]; d3b   = (const float*)d_in[15];
    }
    if (!candB) candB = candA;

    float* outp = (float*)d_out;

    k_zerotail<<<32, 256>>>(outp + XH_ELEMS, out_size > XH_ELEMS ? out_size - XH_ELEMS : 0);  // 1
    k_init<<<1, 32>>>(candA);                                                                  // 2
    k_initcn<<<2, 256>>>(cb);                                                                  // 3
    k_encode<<<MTOT/2, 128>>>(candA, candB, im, c1w, c1b, c2w, c2b, latw, latb);               // 4 (profiled)
    k_vq<<<MTOT/64, 128>>>(cb, im, outp, out_size);                                            // 5
    k_dec<<<MTOT/32, 128>>>(cb, im, d1w, d1b, d2w, d2b, d3w, d3b, candA, candB, outp);         // 6
    k_final<<<1, 1>>>(outp, out_size);                                                         // 7
}